// round 2
// baseline (speedup 1.0000x reference)
#include <cuda_runtime.h>
#include <cuda_bf16.h>
#include <math.h>

#define NN 30000
#define NE 300000
#define NT 3000
#define ET (NE + NN)
#define OUTL 25

// ---------------- scratch (static device allocations; no cudaMalloc) ----------
__device__ float d_h[NN * 128];
__device__ float d_gh[NN * 384];
__device__ float d_lh[NN * 128];
__device__ float d_hist[NN * 128];
__device__ float d_feat[NN * 384];
__device__ float d_gat1[NN * 384];
__device__ float d_gat2[NN * 384];
__device__ float d_ssrc[NN * 3];
__device__ float d_sdst[NN * 3];
__device__ float d_ev[ET * 3];
__device__ int   d_deg[NN];
__device__ int   d_off[NN + 1];
__device__ int   d_cur[NN];
__device__ int   d_eid[ET];
__device__ float d_encT[NT * 384];
__device__ float d_enc[NT * 128];
__device__ float d_xb0[NT * 1024];
__device__ float d_g0[NT * 1024];
__device__ float d_ga[NT * 1024];
__device__ float d_gb[NT * 1024];
__device__ float d_h0[NT * 256];
__device__ float d_c0[NT * 256];
__device__ float d_h1[NT * 256];
__device__ float d_c1[NT * 256];
__device__ float d_h1all[NT * OUTL * 256];

__device__ __forceinline__ float sigm(float x) { return 1.f / (1.f + __expf(-x)); }
__device__ __forceinline__ float lk1(float x) { return x >= 0.f ? x : 0.1f * x; }

// ---------------- generic SGEMM: C[M,N] = A[M,K] @ B[K,N] (+bias)(+leaky 0.1) --
// Requires N % 128 == 0, K % 8 == 0. M guarded.
template <int ACT, bool BIAS>
__global__ void sgemm_kernel(const float* __restrict__ A, const float* __restrict__ B,
                             const float* __restrict__ bias, float* __restrict__ C,
                             int M, int N, int K) {
    __shared__ float As[8][128];
    __shared__ float Bs[8][128];
    const int bn = blockIdx.x * 128;
    const int bm = blockIdx.y * 128;
    const int tid = threadIdx.x;
    const int tx = tid & 15;
    const int ty = tid >> 4;
    const int arow = tid >> 1;
    const int acol = (tid & 1) * 4;
    const int brow = tid >> 5;
    const int bcol = (tid & 31) * 4;

    float acc[8][8];
#pragma unroll
    for (int i = 0; i < 8; i++)
#pragma unroll
        for (int j = 0; j < 8; j++) acc[i][j] = 0.f;

    for (int k0 = 0; k0 < K; k0 += 8) {
        float4 av = make_float4(0.f, 0.f, 0.f, 0.f);
        if (bm + arow < M)
            av = *(const float4*)(A + (size_t)(bm + arow) * K + k0 + acol);
        As[acol + 0][arow] = av.x;
        As[acol + 1][arow] = av.y;
        As[acol + 2][arow] = av.z;
        As[acol + 3][arow] = av.w;
        float4 bv = *(const float4*)(B + (size_t)(k0 + brow) * N + bn + bcol);
        *(float4*)(&Bs[brow][bcol]) = bv;
        __syncthreads();
#pragma unroll
        for (int kk = 0; kk < 8; kk++) {
            float a[8], b[8];
#pragma unroll
            for (int i = 0; i < 8; i++) a[i] = As[kk][ty * 8 + i];
#pragma unroll
            for (int j = 0; j < 8; j++) b[j] = Bs[kk][tx * 8 + j];
#pragma unroll
            for (int i = 0; i < 8; i++)
#pragma unroll
                for (int j = 0; j < 8; j++) acc[i][j] = fmaf(a[i], b[j], acc[i][j]);
        }
        __syncthreads();
    }
#pragma unroll
    for (int i = 0; i < 8; i++) {
        int row = bm + ty * 8 + i;
        if (row >= M) break;
#pragma unroll
        for (int j = 0; j < 8; j++) {
            int col = bn + tx * 8 + j;
            float v = acc[i][j];
            if (BIAS) v += bias[col];
            if (ACT == 1) v = lk1(v);
            C[(size_t)row * N + col] = v;
        }
    }
}

// ---------------- small kernels -----------------------------------------------
__global__ void fzero(float* p, int n) {
    int i = blockIdx.x * blockDim.x + threadIdx.x;
    if (i < n) p[i] = 0.f;
}
__global__ void izero(int* p, int n) {
    int i = blockIdx.x * blockDim.x + threadIdx.x;
    if (i < n) p[i] = 0;
}
__global__ void k_leaky(const float* in, float* out, int n) {
    int i = blockIdx.x * blockDim.x + threadIdx.x;
    if (i < n) out[i] = lk1(in[i]);
}

// GRU step: fused input projection (x -> emb(32) -> gx(384)) + gate combine.
// One block per node, 128 threads.
__global__ void gru_step(const float* __restrict__ x, const float* __restrict__ ipW,
                         const float* __restrict__ ipb, const float* __restrict__ Wx,
                         const float* __restrict__ bx, const float* __restrict__ bh,
                         int t) {
    __shared__ float emb[32];
    int n = blockIdx.x;
    int j = threadIdx.x;
    if (j < 32) {
        float x0 = x[n * 32 + t * 2];
        float x1 = x[n * 32 + t * 2 + 1];
        emb[j] = lk1(x0 * ipW[j] + x1 * ipW[32 + j] + ipb[j]);
    }
    __syncthreads();
    float gr = bx[j], gz = bx[128 + j], gn = bx[256 + j];
#pragma unroll 8
    for (int d = 0; d < 32; d++) {
        float e = emb[d];
        const float* w = Wx + d * 384;
        gr = fmaf(e, w[j], gr);
        gz = fmaf(e, w[128 + j], gz);
        gn = fmaf(e, w[256 + j], gn);
    }
    size_t gb = (size_t)n * 384;
    float hr = d_gh[gb + j] + bh[j];
    float hz = d_gh[gb + 128 + j] + bh[128 + j];
    float hn = d_gh[gb + 256 + j] + bh[256 + j];
    float r = sigm(gr + hr);
    float z = sigm(gz + hz);
    float nn = tanhf(gn + r * hn);
    size_t hi = (size_t)n * 128 + j;
    d_h[hi] = (1.f - z) * nn + z * d_h[hi];
}

// ---------------- CSR build (deterministic after sort) -------------------------
__global__ void k_deg(const int* __restrict__ ei) {
    int e = blockIdx.x * blockDim.x + threadIdx.x;
    if (e >= ET) return;
    int d = e < NE ? ei[NE + e] : e - NE;
    atomicAdd(&d_deg[d], 1);
}
__global__ void k_scan() {
    __shared__ int sums[1024];
    const int CH = (NN + 1023) / 1024;
    int t = threadIdx.x;
    int begin = t * CH;
    int s = 0;
    for (int i = 0; i < CH; i++) {
        int idx = begin + i;
        if (idx < NN) s += d_deg[idx];
    }
    sums[t] = s;
    __syncthreads();
    for (int off = 1; off < 1024; off <<= 1) {
        int v = sums[t];
        int add = (t >= off) ? sums[t - off] : 0;
        __syncthreads();
        sums[t] = v + add;
        __syncthreads();
    }
    int run = (t == 0) ? 0 : sums[t - 1];
    for (int i = 0; i < CH; i++) {
        int idx = begin + i;
        if (idx < NN) {
            d_off[idx] = run;
            run += d_deg[idx];
        }
    }
    if (t == 1023) d_off[NN] = sums[1023];
}
__global__ void k_fill(const int* __restrict__ ei) {
    int e = blockIdx.x * blockDim.x + threadIdx.x;
    if (e >= ET) return;
    int d = e < NE ? ei[NE + e] : e - NE;
    int p = atomicAdd(&d_cur[d], 1);
    d_eid[d_off[d] + p] = e;
}
__global__ void k_sort() {
    int d = blockIdx.x * blockDim.x + threadIdx.x;
    if (d >= NN) return;
    int b = d_off[d], e = d_off[d + 1];
    for (int i = b + 1; i < e; i++) {
        int key = d_eid[i];
        int j = i - 1;
        while (j >= b && d_eid[j] > key) {
            d_eid[j + 1] = d_eid[j];
            j--;
        }
        d_eid[j + 1] = key;
    }
}

// ---------------- GAT ----------------------------------------------------------
// per-node per-head attention scores (3 warps per block of 96 threads)
__global__ void gat_scores(const float* __restrict__ feat, const float* __restrict__ as,
                           const float* __restrict__ ad) {
    int n = blockIdx.x;
    int wid = threadIdx.x >> 5, lane = threadIdx.x & 31;
    const float* f = feat + (size_t)n * 384 + wid * 128;
    const float* A = as + wid * 128;
    const float* D = ad + wid * 128;
    float s = 0.f, d = 0.f;
#pragma unroll
    for (int k = lane; k < 128; k += 32) {
        float v = f[k];
        s += v * A[k];
        d += v * D[k];
    }
#pragma unroll
    for (int o = 16; o; o >>= 1) {
        s += __shfl_xor_sync(0xffffffffu, s, o);
        d += __shfl_xor_sync(0xffffffffu, d, o);
    }
    if (!lane) {
        d_ssrc[n * 3 + wid] = s;
        d_sdst[n * 3 + wid] = d;
    }
}
__global__ void edge_scores(const int* __restrict__ ei) {
    int e = blockIdx.x * blockDim.x + threadIdx.x;
    if (e >= ET) return;
    int s = e < NE ? ei[e] : e - NE;
    int d = e < NE ? ei[NE + e] : e - NE;
#pragma unroll
    for (int h = 0; h < 3; h++) {
        float v = d_ssrc[s * 3 + h] + d_sdst[d * 3 + h];
        d_ev[e * 3 + h] = v >= 0.f ? v : 0.2f * v;
    }
}
// one warp per (dst, head): softmax over in-edges + weighted feature sum
__global__ void gat_aggregate(const int* __restrict__ ei, const float* __restrict__ feat,
                              const float* __restrict__ bias, float* __restrict__ out) {
    int gw = (blockIdx.x * blockDim.x + threadIdx.x) >> 5;
    int lane = threadIdx.x & 31;
    if (gw >= NN * 3) return;
    int dst = gw / 3, hd = gw % 3;
    int b = d_off[dst], en = d_off[dst + 1];
    float m = -1e30f;
    for (int i = b; i < en; i++) m = fmaxf(m, d_ev[d_eid[i] * 3 + hd]);
    float denom = 0.f, a0 = 0.f, a1 = 0.f, a2 = 0.f, a3 = 0.f;
    for (int i = b; i < en; i++) {
        int e = d_eid[i];
        float w = __expf(d_ev[e * 3 + hd] - m);
        denom += w;
        int s = e < NE ? ei[e] : e - NE;
        const float* fr = feat + (size_t)s * 384 + hd * 128;
        a0 = fmaf(w, fr[lane], a0);
        a1 = fmaf(w, fr[lane + 32], a1);
        a2 = fmaf(w, fr[lane + 64], a2);
        a3 = fmaf(w, fr[lane + 96], a3);
    }
    float inv = 1.f / denom;
    size_t ob = (size_t)dst * 384 + hd * 128;
    out[ob + lane] = a0 * inv + bias[hd * 128 + lane];
    out[ob + lane + 32] = a1 * inv + bias[hd * 128 + lane + 32];
    out[ob + lane + 64] = a2 * inv + bias[hd * 128 + lane + 64];
    out[ob + lane + 96] = a3 * inv + bias[hd * 128 + lane + 96];
}

__global__ void k_gather(const int* __restrict__ tgt, const float* __restrict__ src,
                         float* __restrict__ dst) {
    int i = blockIdx.x * blockDim.x + threadIdx.x;
    if (i >= NT * 384) return;
    int r = i / 384, c = i - r * 384;
    dst[i] = src[(size_t)tgt[r] * 384 + c];
}

// ---------------- LSTM decoder pointwise ---------------------------------------
__global__ void lstm_combine(const float* __restrict__ gx, const float* __restrict__ gh,
                             float* __restrict__ h, float* __restrict__ c,
                             float* __restrict__ hall, int t) {
    int idx = blockIdx.x * blockDim.x + threadIdx.x;
    if (idx >= NT * 256) return;
    int i = idx >> 8, j = idx & 255;
    size_t base = (size_t)i * 1024;
    float gi = gx[base + j] + gh[base + j];
    float gf = gx[base + 256 + j] + gh[base + 256 + j];
    float gg = gx[base + 512 + j] + gh[base + 512 + j];
    float go = gx[base + 768 + j] + gh[base + 768 + j];
    float cv = sigm(gf) * c[idx] + sigm(gi) * tanhf(gg);
    float hv = sigm(go) * tanhf(cv);
    c[idx] = cv;
    h[idx] = hv;
    if (hall) hall[((size_t)i * OUTL + t) * 256 + j] = hv;
}

// output head: out[r,0:2] = h1all[r,:] @ op_W + op_b ; one warp per row
__global__ void out_head(const float* __restrict__ opW, const float* __restrict__ opb,
                         float* __restrict__ out) {
    int gw = (blockIdx.x * blockDim.x + threadIdx.x) >> 5;
    int lane = threadIdx.x & 31;
    if (gw >= NT * OUTL) return;
    const float* hr = d_h1all + (size_t)gw * 256;
    float s0 = 0.f, s1 = 0.f;
#pragma unroll
    for (int k = lane; k < 256; k += 32) {
        float h = hr[k];
        s0 = fmaf(h, opW[k * 2], s0);
        s1 = fmaf(h, opW[k * 2 + 1], s1);
    }
#pragma unroll
    for (int o = 16; o; o >>= 1) {
        s0 += __shfl_xor_sync(0xffffffffu, s0, o);
        s1 += __shfl_xor_sync(0xffffffffu, s1, o);
    }
    if (!lane) {
        out[(size_t)gw * 2] = s0 + opb[0];
        out[(size_t)gw * 2 + 1] = s1 + opb[1];
    }
}

// ---------------- host orchestration -------------------------------------------
static void sgemm(const float* A, const float* B, const float* bias, float* C,
                  int M, int N, int K, int act, bool hasbias) {
    dim3 g(N / 128, (M + 127) / 128);
    if (hasbias) {
        if (act) sgemm_kernel<1, true><<<g, 256>>>(A, B, bias, C, M, N, K);
        else     sgemm_kernel<0, true><<<g, 256>>>(A, B, bias, C, M, N, K);
    } else {
        if (act) sgemm_kernel<1, false><<<g, 256>>>(A, B, bias, C, M, N, K);
        else     sgemm_kernel<0, false><<<g, 256>>>(A, B, bias, C, M, N, K);
    }
}

template <typename T>
static T* symptr(const void* sym) {
    void* p = nullptr;
    cudaGetSymbolAddress(&p, sym);
    return (T*)p;
}

extern "C" void kernel_launch(void* const* d_in, const int* in_sizes, int n_in,
                              void* d_out, int out_size) {
    const float* x    = (const float*)d_in[0];
    const int*   ei   = (const int*)d_in[1];
    const int*   tgt  = (const int*)d_in[2];
    const float* ipW  = (const float*)d_in[3];
    const float* ipb  = (const float*)d_in[4];
    const float* gWx  = (const float*)d_in[5];
    const float* gWh  = (const float*)d_in[6];
    const float* gbx  = (const float*)d_in[7];
    const float* gbh  = (const float*)d_in[8];
    const float* dynW = (const float*)d_in[9];
    const float* dynb = (const float*)d_in[10];
    const float* g1W  = (const float*)d_in[11];
    const float* g1as = (const float*)d_in[12];
    const float* g1ad = (const float*)d_in[13];
    const float* g1b  = (const float*)d_in[14];
    const float* g2W  = (const float*)d_in[15];
    const float* g2as = (const float*)d_in[16];
    const float* g2ad = (const float*)d_in[17];
    const float* g2b  = (const float*)d_in[18];
    const float* fcW  = (const float*)d_in[19];
    const float* fcb  = (const float*)d_in[20];
    const float* l0Wx = (const float*)d_in[21];
    const float* l0Wh = (const float*)d_in[22];
    const float* l0b  = (const float*)d_in[23];
    const float* l1Wx = (const float*)d_in[24];
    const float* l1Wh = (const float*)d_in[25];
    const float* l1b  = (const float*)d_in[26];
    const float* opW  = (const float*)d_in[27];
    const float* opb  = (const float*)d_in[28];
    float* out = (float*)d_out;

    float* p_h    = symptr<float>(d_h);
    float* p_gh   = symptr<float>(d_gh);
    float* p_lh   = symptr<float>(d_lh);
    float* p_hist = symptr<float>(d_hist);
    float* p_feat = symptr<float>(d_feat);
    float* p_gat1 = symptr<float>(d_gat1);
    float* p_gat2 = symptr<float>(d_gat2);
    float* p_encT = symptr<float>(d_encT);
    float* p_enc  = symptr<float>(d_enc);
    float* p_xb0  = symptr<float>(d_xb0);
    float* p_g0   = symptr<float>(d_g0);
    float* p_ga   = symptr<float>(d_ga);
    float* p_gb   = symptr<float>(d_gb);
    float* p_h0   = symptr<float>(d_h0);
    float* p_c0   = symptr<float>(d_c0);
    float* p_h1   = symptr<float>(d_h1);
    float* p_c1   = symptr<float>(d_c1);
    int*   p_deg  = symptr<int>(d_deg);
    int*   p_cur  = symptr<int>(d_cur);

    // ---- CSR build (depends only on edge_index) ----
    izero<<<(NN + 255) / 256, 256>>>(p_deg, NN);
    izero<<<(NN + 255) / 256, 256>>>(p_cur, NN);
    k_deg<<<(ET + 255) / 256, 256>>>(ei);
    k_scan<<<1, 1024>>>();
    k_fill<<<(ET + 255) / 256, 256>>>(ei);
    k_sort<<<(NN + 255) / 256, 256>>>();

    // ---- GRU encoder ----
    fzero<<<(NN * 128 + 255) / 256, 256>>>(p_h, NN * 128);
    for (int t = 0; t < 16; t++) {
        sgemm(p_h, gWh, nullptr, p_gh, NN, 384, 128, 0, false);
        gru_step<<<NN, 128>>>(x, ipW, ipb, gWx, gbx, gbh, t);
    }
    k_leaky<<<(NN * 128 + 255) / 256, 256>>>(p_h, p_lh, NN * 128);
    sgemm(p_lh, dynW, dynb, p_hist, NN, 128, 128, 1, true);

    // ---- GAT layer 1 ----
    sgemm(p_hist, g1W, nullptr, p_feat, NN, 384, 128, 0, false);
    gat_scores<<<NN, 96>>>(p_feat, g1as, g1ad);
    edge_scores<<<(ET + 255) / 256, 256>>>(ei);
    gat_aggregate<<<(NN * 3 + 3) / 4, 128>>>(ei, p_feat, g1b, p_gat1);

    // ---- GAT layer 2 ----
    sgemm(p_gat1, g2W, nullptr, p_feat, NN, 384, 384, 0, false);
    gat_scores<<<NN, 96>>>(p_feat, g2as, g2ad);
    edge_scores<<<(ET + 255) / 256, 256>>>(ei);
    gat_aggregate<<<(NN * 3 + 3) / 4, 128>>>(ei, p_feat, g2b, p_gat2);

    // ---- target gather + fc ----
    k_gather<<<(NT * 384 + 255) / 256, 256>>>(tgt, p_gat2, p_encT);
    sgemm(p_encT, fcW, fcb, p_enc, NT, 128, 384, 1, true);

    // ---- decoder ----
    sgemm(p_enc, l0Wx, l0b, p_xb0, NT, 1024, 128, 0, true);  // constant over t
    fzero<<<(NT * 256 + 255) / 256, 256>>>(p_h0, NT * 256);
    fzero<<<(NT * 256 + 255) / 256, 256>>>(p_c0, NT * 256);
    fzero<<<(NT * 256 + 255) / 256, 256>>>(p_h1, NT * 256);
    fzero<<<(NT * 256 + 255) / 256, 256>>>(p_c1, NT * 256);
    for (int t = 0; t < OUTL; t++) {
        sgemm(p_h0, l0Wh, nullptr, p_g0, NT, 1024, 256, 0, false);
        lstm_combine<<<(NT * 256 + 255) / 256, 256>>>(p_xb0, p_g0, p_h0, p_c0, nullptr, t);
        sgemm(p_h0, l1Wx, l1b, p_ga, NT, 1024, 256, 0, true);
        sgemm(p_h1, l1Wh, nullptr, p_gb, NT, 1024, 256, 0, false);
        lstm_combine<<<(NT * 256 + 255) / 256, 256>>>(p_ga, p_gb, p_h1, p_c1,
                                                      symptr<float>(d_h1all), t);
    }
    // one warp per output row: NT*OUTL warps total
    out_head<<<(NT * OUTL * 32 + 127) / 128, 128>>>(opW, opb, out);
}

// round 4
// speedup vs baseline: 1.3504x; 1.3504x over previous
#include <cuda_runtime.h>
#include <cuda_bf16.h>
#include <math.h>

#define NN 30000
#define NE 300000
#define NT 3000
#define ET (NE + NN)
#define OUTL 25

typedef unsigned long long ull;

// ---------------- scratch ------------------------------------------------------
__device__ float d_lh[NN * 128];
__device__ float d_hist[NN * 128];
__device__ float d_feat[NN * 384];
__device__ float d_gat1[NN * 384];
__device__ float d_gat2[NN * 384];
__device__ float d_ssrc[NN * 3];
__device__ float d_sdst[NN * 3];
__device__ float d_ev[ET * 3];
__device__ int   d_deg[NN];
__device__ int   d_off[NN + 1];
__device__ int   d_cur[NN];
__device__ int   d_eid[ET];
__device__ float d_encT[NT * 384];
__device__ float d_enc[NT * 128];
__device__ float d_xb0[NT * 1024];
__device__ float d_h1all[NT * OUTL * 256];

__device__ __forceinline__ float sigm(float x) { return 1.f / (1.f + __expf(-x)); }
__device__ __forceinline__ float lk1(float x) { return x >= 0.f ? x : 0.1f * x; }

// ---- packed fp32x2 helpers (Blackwell sm_100+) --------------------------------
__device__ __forceinline__ ull pdup(float w) {
    unsigned u = __float_as_uint(w);
    ull r;
    asm("mov.b64 %0, {%1, %1};" : "=l"(r) : "r"(u));
    return r;
}
__device__ __forceinline__ ull pk2(float a, float b) {
    unsigned ua = __float_as_uint(a), ub = __float_as_uint(b);
    ull r;
    asm("mov.b64 %0, {%1, %2};" : "=l"(r) : "r"(ua), "r"(ub));
    return r;
}
__device__ __forceinline__ float2 unpk(ull v) {
    unsigned a, b;
    asm("mov.b64 {%0, %1}, %2;" : "=r"(a), "=r"(b) : "l"(v));
    return make_float2(__uint_as_float(a), __uint_as_float(b));
}
__device__ __forceinline__ void fma2(ull& acc, ull a, ull b) {
    asm("fma.rn.f32x2 %0, %1, %2, %0;" : "+l"(acc) : "l"(a), "l"(b));
}

// ---------------- generic SGEMM with f32x2 microkernel -------------------------
// C[M,N] = A[M,K] @ B[K,N] (+bias)(+leaky). N%128==0, K%8==0, M guarded.
template <int ACT, bool BIAS>
__global__ void sgemm_kernel(const float* __restrict__ A, const float* __restrict__ B,
                             const float* __restrict__ bias, float* __restrict__ C,
                             int M, int N, int K) {
    __shared__ __align__(16) float As[8][128];
    __shared__ __align__(16) float Bs[8][128];
    const int bn = blockIdx.x * 128;
    const int bm = blockIdx.y * 128;
    const int tid = threadIdx.x;
    const int tx = tid & 15;
    const int ty = tid >> 4;
    const int arow = tid >> 1;
    const int acol = (tid & 1) * 4;
    const int brow = tid >> 5;
    const int bcol = (tid & 31) * 4;

    ull acc[8][4];
#pragma unroll
    for (int i = 0; i < 8; i++)
#pragma unroll
        for (int j = 0; j < 4; j++) acc[i][j] = 0ULL;

    for (int k0 = 0; k0 < K; k0 += 8) {
        float4 av = make_float4(0.f, 0.f, 0.f, 0.f);
        if (bm + arow < M)
            av = *(const float4*)(A + (size_t)(bm + arow) * K + k0 + acol);
        As[acol + 0][arow] = av.x;
        As[acol + 1][arow] = av.y;
        As[acol + 2][arow] = av.z;
        As[acol + 3][arow] = av.w;
        float4 bv = *(const float4*)(B + (size_t)(k0 + brow) * N + bn + bcol);
        *(float4*)(&Bs[brow][bcol]) = bv;
        __syncthreads();
#pragma unroll
        for (int kk = 0; kk < 8; kk++) {
            ull a2[8], b2[4];
#pragma unroll
            for (int i = 0; i < 8; i++) a2[i] = pdup(As[kk][ty * 8 + i]);
#pragma unroll
            for (int j = 0; j < 4; j++) b2[j] = *(const ull*)(&Bs[kk][tx * 8 + j * 2]);
#pragma unroll
            for (int i = 0; i < 8; i++)
#pragma unroll
                for (int j = 0; j < 4; j++) fma2(acc[i][j], a2[i], b2[j]);
        }
        __syncthreads();
    }
#pragma unroll
    for (int i = 0; i < 8; i++) {
        int row = bm + ty * 8 + i;
        if (row >= M) break;
#pragma unroll
        for (int j = 0; j < 4; j++) {
            float2 v = unpk(acc[i][j]);
            int col = bn + tx * 8 + j * 2;
            float v0 = v.x, v1 = v.y;
            if (BIAS) { v0 += bias[col]; v1 += bias[col + 1]; }
            if (ACT == 1) { v0 = lk1(v0); v1 = lk1(v1); }
            C[(size_t)row * N + col] = v0;
            C[(size_t)row * N + col + 1] = v1;
        }
    }
}

__global__ void izero(int* p, int n) {
    int i = blockIdx.x * blockDim.x + threadIdx.x;
    if (i < n) p[i] = 0;
}

// ---------------- persistent GRU encoder ---------------------------------------
// 24 rows/block, 1250 blocks, 256 threads. Wh cached in smem (196 KB).
// thread = (half, col j): owns hidden col j, 6 row-pairs of its half.
#define GR 24
#define GP 12
#define GHP 6
__global__ __launch_bounds__(256, 1) void gru_kernel(
    const float* __restrict__ x, const float* __restrict__ ipW,
    const float* __restrict__ ipb, const float* __restrict__ Wx,
    const float* __restrict__ bx, const float* __restrict__ bh,
    const float* __restrict__ Wh, float* __restrict__ lh) {
    extern __shared__ float smem[];
    float* Whs = smem;                         // 128*384 floats
    ull* hs = (ull*)(smem + 128 * 384);        // [128][GP] row-pairs
    ull* es = hs + 128 * GP;                   // [32][GP]
    const int tid = threadIdx.x;
    const int half = tid >> 7, j = tid & 127;
    const int row0 = blockIdx.x * GR;

    for (int i = tid * 4; i < 128 * 384; i += 1024)
        *(float4*)(Whs + i) = *(const float4*)(Wh + i);
    for (int i = tid; i < 128 * GP; i += 256) hs[i] = 0ULL;

    ull bh2[3], bx2[3];
#pragma unroll
    for (int g = 0; g < 3; g++) {
        bh2[g] = pdup(bh[g * 128 + j]);
        bx2[g] = pdup(bx[g * 128 + j]);
    }
    __syncthreads();

    for (int t = 0; t < 16; t++) {
        // input embedding, column-major [32][24] floats = [32][GP] pairs
        for (int v = tid; v < GR * 32; v += 256) {
            int r = v >> 5, c = v & 31;
            float x0 = x[(size_t)(row0 + r) * 32 + t * 2];
            float x1 = x[(size_t)(row0 + r) * 32 + t * 2 + 1];
            ((float*)es)[c * GR + r] = lk1(fmaf(x0, ipW[c], fmaf(x1, ipW[32 + c], ipb[c])));
        }
        __syncthreads();

        ull ah[3][GHP], ax[3][GHP];
#pragma unroll
        for (int g = 0; g < 3; g++)
#pragma unroll
            for (int p = 0; p < GHP; p++) { ah[g][p] = bh2[g]; ax[g][p] = bx2[g]; }

#pragma unroll 2
        for (int k = 0; k < 128; k++) {
            ull wr = pdup(Whs[k * 384 + j]);
            ull wz = pdup(Whs[k * 384 + 128 + j]);
            ull wn = pdup(Whs[k * 384 + 256 + j]);
#pragma unroll
            for (int p = 0; p < GHP; p++) {
                ull h2 = hs[k * GP + half * GHP + p];
                fma2(ah[0][p], h2, wr);
                fma2(ah[1][p], h2, wz);
                fma2(ah[2][p], h2, wn);
            }
        }
#pragma unroll 2
        for (int k = 0; k < 32; k++) {
            ull wr = pdup(Wx[k * 384 + j]);
            ull wz = pdup(Wx[k * 384 + 128 + j]);
            ull wn = pdup(Wx[k * 384 + 256 + j]);
#pragma unroll
            for (int p = 0; p < GHP; p++) {
                ull e2 = es[k * GP + half * GHP + p];
                fma2(ax[0][p], e2, wr);
                fma2(ax[1][p], e2, wz);
                fma2(ax[2][p], e2, wn);
            }
        }
        __syncthreads();   // all reads of hs/es complete before overwrite
#pragma unroll
        for (int p = 0; p < GHP; p++) {
            float2 hr = unpk(ah[0][p]), hz = unpk(ah[1][p]), hn = unpk(ah[2][p]);
            float2 xr = unpk(ax[0][p]), xz = unpk(ax[1][p]), xn = unpk(ax[2][p]);
            float2 ho = unpk(hs[j * GP + half * GHP + p]);  // my cell only
            float r0 = sigm(xr.x + hr.x), r1 = sigm(xr.y + hr.y);
            float z0 = sigm(xz.x + hz.x), z1 = sigm(xz.y + hz.y);
            float n0 = tanhf(xn.x + r0 * hn.x), n1 = tanhf(xn.y + r1 * hn.y);
            float h0 = (1.f - z0) * n0 + z0 * ho.x;
            float h1 = (1.f - z1) * n1 + z1 * ho.y;
            hs[j * GP + half * GHP + p] = pk2(h0, h1);
        }
        __syncthreads();
    }
    // write leaky(h)
#pragma unroll
    for (int p = 0; p < GHP; p++) {
        float2 h = unpk(hs[j * GP + half * GHP + p]);
        int r = row0 + 2 * (half * GHP + p);
        lh[(size_t)r * 128 + j] = lk1(h.x);
        lh[(size_t)(r + 1) * 128 + j] = lk1(h.y);
    }
}

// ---------------- persistent LSTM decoder --------------------------------------
// 24 rows/block, 125 blocks, 256 threads. thread j owns hidden col j (all 12 pairs).
#define DR 24
#define DP 12
__global__ __launch_bounds__(256, 1) void decoder_kernel(
    const float* __restrict__ xb0, const float* __restrict__ Wh0,
    const float* __restrict__ Wx1, const float* __restrict__ Wh1,
    const float* __restrict__ b1, float* __restrict__ h1all) {
    extern __shared__ ull dsm[];
    ull* xb0p = dsm;                 // [1024][DP]
    ull* h0s = xb0p + 1024 * DP;     // [256][DP]
    ull* h1s = h0s + 256 * DP;       // [256][DP]
    const int tid = threadIdx.x;
    const int row0 = blockIdx.x * DR;

    for (int idx = tid; idx < 1024 * DP; idx += 256) {
        int col = idx / DP, p = idx - col * DP;
        xb0p[idx] = pk2(xb0[(size_t)(row0 + 2 * p) * 1024 + col],
                        xb0[(size_t)(row0 + 2 * p + 1) * 1024 + col]);
    }
    for (int i = tid; i < 256 * DP; i += 256) { h0s[i] = 0ULL; h1s[i] = 0ULL; }

    ull b12[4];
#pragma unroll
    for (int g = 0; g < 4; g++) b12[g] = pdup(b1[g * 256 + tid]);

    float c0a[DP], c0b[DP], c1a[DP], c1b[DP];
#pragma unroll
    for (int p = 0; p < DP; p++) { c0a[p] = c0b[p] = c1a[p] = c1b[p] = 0.f; }
    __syncthreads();

    for (int t = 0; t < OUTL; t++) {
        // ---- layer 0: gates = xb0 + h0_prev @ Wh0 ----
        ull acc[4][DP];
#pragma unroll
        for (int g = 0; g < 4; g++)
#pragma unroll
            for (int p = 0; p < DP; p++) acc[g][p] = xb0p[(g * 256 + tid) * DP + p];
#pragma unroll 2
        for (int k = 0; k < 256; k++) {
            ull w0 = pdup(Wh0[k * 1024 + tid]);
            ull w1 = pdup(Wh0[k * 1024 + 256 + tid]);
            ull w2 = pdup(Wh0[k * 1024 + 512 + tid]);
            ull w3 = pdup(Wh0[k * 1024 + 768 + tid]);
#pragma unroll
            for (int p = 0; p < DP; p++) {
                ull h2 = h0s[k * DP + p];
                fma2(acc[0][p], h2, w0);
                fma2(acc[1][p], h2, w1);
                fma2(acc[2][p], h2, w2);
                fma2(acc[3][p], h2, w3);
            }
        }
        float h0na[DP], h0nb[DP];
#pragma unroll
        for (int p = 0; p < DP; p++) {
            float2 vi = unpk(acc[0][p]), vf = unpk(acc[1][p]);
            float2 vg = unpk(acc[2][p]), vo = unpk(acc[3][p]);
            c0a[p] = sigm(vf.x) * c0a[p] + sigm(vi.x) * tanhf(vg.x);
            c0b[p] = sigm(vf.y) * c0b[p] + sigm(vi.y) * tanhf(vg.y);
            h0na[p] = sigm(vo.x) * tanhf(c0a[p]);
            h0nb[p] = sigm(vo.y) * tanhf(c0b[p]);
        }
        __syncthreads();
#pragma unroll
        for (int p = 0; p < DP; p++) h0s[tid * DP + p] = pk2(h0na[p], h0nb[p]);
        __syncthreads();

        // ---- layer 1: gates = h0_new @ Wx1 + h1_prev @ Wh1 + b1 ----
#pragma unroll
        for (int g = 0; g < 4; g++)
#pragma unroll
            for (int p = 0; p < DP; p++) acc[g][p] = b12[g];
#pragma unroll 2
        for (int k = 0; k < 256; k++) {
            ull w0 = pdup(Wx1[k * 1024 + tid]);
            ull w1 = pdup(Wx1[k * 1024 + 256 + tid]);
            ull w2 = pdup(Wx1[k * 1024 + 512 + tid]);
            ull w3 = pdup(Wx1[k * 1024 + 768 + tid]);
#pragma unroll
            for (int p = 0; p < DP; p++) {
                ull h2 = h0s[k * DP + p];
                fma2(acc[0][p], h2, w0);
                fma2(acc[1][p], h2, w1);
                fma2(acc[2][p], h2, w2);
                fma2(acc[3][p], h2, w3);
            }
        }
#pragma unroll 2
        for (int k = 0; k < 256; k++) {
            ull w0 = pdup(Wh1[k * 1024 + tid]);
            ull w1 = pdup(Wh1[k * 1024 + 256 + tid]);
            ull w2 = pdup(Wh1[k * 1024 + 512 + tid]);
            ull w3 = pdup(Wh1[k * 1024 + 768 + tid]);
#pragma unroll
            for (int p = 0; p < DP; p++) {
                ull h2 = h1s[k * DP + p];
                fma2(acc[0][p], h2, w0);
                fma2(acc[1][p], h2, w1);
                fma2(acc[2][p], h2, w2);
                fma2(acc[3][p], h2, w3);
            }
        }
        float h1na[DP], h1nb[DP];
#pragma unroll
        for (int p = 0; p < DP; p++) {
            float2 vi = unpk(acc[0][p]), vf = unpk(acc[1][p]);
            float2 vg = unpk(acc[2][p]), vo = unpk(acc[3][p]);
            c1a[p] = sigm(vf.x) * c1a[p] + sigm(vi.x) * tanhf(vg.x);
            c1b[p] = sigm(vf.y) * c1b[p] + sigm(vi.y) * tanhf(vg.y);
            h1na[p] = sigm(vo.x) * tanhf(c1a[p]);
            h1nb[p] = sigm(vo.y) * tanhf(c1b[p]);
            int r = row0 + 2 * p;
            h1all[((size_t)r * OUTL + t) * 256 + tid] = h1na[p];
            h1all[((size_t)(r + 1) * OUTL + t) * 256 + tid] = h1nb[p];
        }
        __syncthreads();
#pragma unroll
        for (int p = 0; p < DP; p++) h1s[tid * DP + p] = pk2(h1na[p], h1nb[p]);
        __syncthreads();
    }
}

// ---------------- CSR build (deterministic after sort) -------------------------
__global__ void k_deg(const int* __restrict__ ei) {
    int e = blockIdx.x * blockDim.x + threadIdx.x;
    if (e >= ET) return;
    int d = e < NE ? ei[NE + e] : e - NE;
    atomicAdd(&d_deg[d], 1);
}
__global__ void k_scan() {
    __shared__ int sums[1024];
    const int CH = (NN + 1023) / 1024;
    int t = threadIdx.x;
    int begin = t * CH;
    int s = 0;
    for (int i = 0; i < CH; i++) {
        int idx = begin + i;
        if (idx < NN) s += d_deg[idx];
    }
    sums[t] = s;
    __syncthreads();
    for (int off = 1; off < 1024; off <<= 1) {
        int v = sums[t];
        int add = (t >= off) ? sums[t - off] : 0;
        __syncthreads();
        sums[t] = v + add;
        __syncthreads();
    }
    int run = (t == 0) ? 0 : sums[t - 1];
    for (int i = 0; i < CH; i++) {
        int idx = begin + i;
        if (idx < NN) {
            d_off[idx] = run;
            run += d_deg[idx];
        }
    }
    if (t == 1023) d_off[NN] = sums[1023];
}
__global__ void k_fill(const int* __restrict__ ei) {
    int e = blockIdx.x * blockDim.x + threadIdx.x;
    if (e >= ET) return;
    int d = e < NE ? ei[NE + e] : e - NE;
    int p = atomicAdd(&d_cur[d], 1);
    d_eid[d_off[d] + p] = e;
}
__global__ void k_sort() {
    int d = blockIdx.x * blockDim.x + threadIdx.x;
    if (d >= NN) return;
    int b = d_off[d], e = d_off[d + 1];
    for (int i = b + 1; i < e; i++) {
        int key = d_eid[i];
        int j = i - 1;
        while (j >= b && d_eid[j] > key) {
            d_eid[j + 1] = d_eid[j];
            j--;
        }
        d_eid[j + 1] = key;
    }
}

// ---------------- GAT ----------------------------------------------------------
__global__ void gat_scores(const float* __restrict__ feat, const float* __restrict__ as,
                           const float* __restrict__ ad) {
    int n = blockIdx.x;
    int wid = threadIdx.x >> 5, lane = threadIdx.x & 31;
    const float* f = feat + (size_t)n * 384 + wid * 128;
    const float* A = as + wid * 128;
    const float* D = ad + wid * 128;
    float s = 0.f, d = 0.f;
#pragma unroll
    for (int k = lane; k < 128; k += 32) {
        float v = f[k];
        s += v * A[k];
        d += v * D[k];
    }
#pragma unroll
    for (int o = 16; o; o >>= 1) {
        s += __shfl_xor_sync(0xffffffffu, s, o);
        d += __shfl_xor_sync(0xffffffffu, d, o);
    }
    if (!lane) {
        d_ssrc[n * 3 + wid] = s;
        d_sdst[n * 3 + wid] = d;
    }
}
__global__ void edge_scores(const int* __restrict__ ei) {
    int e = blockIdx.x * blockDim.x + threadIdx.x;
    if (e >= ET) return;
    int s = e < NE ? ei[e] : e - NE;
    int d = e < NE ? ei[NE + e] : e - NE;
#pragma unroll
    for (int h = 0; h < 3; h++) {
        float v = d_ssrc[s * 3 + h] + d_sdst[d * 3 + h];
        d_ev[e * 3 + h] = v >= 0.f ? v : 0.2f * v;
    }
}
__global__ void gat_aggregate(const int* __restrict__ ei, const float* __restrict__ feat,
                              const float* __restrict__ bias, float* __restrict__ out) {
    int gw = (blockIdx.x * blockDim.x + threadIdx.x) >> 5;
    int lane = threadIdx.x & 31;
    if (gw >= NN * 3) return;
    int dst = gw / 3, hd = gw % 3;
    int b = d_off[dst], en = d_off[dst + 1];
    float m = -1e30f;
    for (int i = b; i < en; i++) m = fmaxf(m, d_ev[d_eid[i] * 3 + hd]);
    float denom = 0.f, a0 = 0.f, a1 = 0.f, a2 = 0.f, a3 = 0.f;
    for (int i = b; i < en; i++) {
        int e = d_eid[i];
        float w = __expf(d_ev[e * 3 + hd] - m);
        denom += w;
        int s = e < NE ? ei[e] : e - NE;
        const float* fr = feat + (size_t)s * 384 + hd * 128;
        a0 = fmaf(w, fr[lane], a0);
        a1 = fmaf(w, fr[lane + 32], a1);
        a2 = fmaf(w, fr[lane + 64], a2);
        a3 = fmaf(w, fr[lane + 96], a3);
    }
    float inv = 1.f / denom;
    size_t ob = (size_t)dst * 384 + hd * 128;
    out[ob + lane] = a0 * inv + bias[hd * 128 + lane];
    out[ob + lane + 32] = a1 * inv + bias[hd * 128 + lane + 32];
    out[ob + lane + 64] = a2 * inv + bias[hd * 128 + lane + 64];
    out[ob + lane + 96] = a3 * inv + bias[hd * 128 + lane + 96];
}

__global__ void k_gather(const int* __restrict__ tgt, const float* __restrict__ src,
                         float* __restrict__ dst) {
    int i = blockIdx.x * blockDim.x + threadIdx.x;
    if (i >= NT * 384) return;
    int r = i / 384, c = i - r * 384;
    dst[i] = src[(size_t)tgt[r] * 384 + c];
}

// output head
__global__ void out_head(const float* __restrict__ opW, const float* __restrict__ opb,
                         float* __restrict__ out) {
    int gw = (blockIdx.x * blockDim.x + threadIdx.x) >> 5;
    int lane = threadIdx.x & 31;
    if (gw >= NT * OUTL) return;
    const float* hr = d_h1all + (size_t)gw * 256;
    float s0 = 0.f, s1 = 0.f;
#pragma unroll
    for (int k = lane; k < 256; k += 32) {
        float h = hr[k];
        s0 = fmaf(h, opW[k * 2], s0);
        s1 = fmaf(h, opW[k * 2 + 1], s1);
    }
#pragma unroll
    for (int o = 16; o; o >>= 1) {
        s0 += __shfl_xor_sync(0xffffffffu, s0, o);
        s1 += __shfl_xor_sync(0xffffffffu, s1, o);
    }
    if (!lane) {
        out[(size_t)gw * 2] = s0 + opb[0];
        out[(size_t)gw * 2 + 1] = s1 + opb[1];
    }
}

// ---------------- host orchestration -------------------------------------------
static void sgemm(const float* A, const float* B, const float* bias, float* C,
                  int M, int N, int K, int act, bool hasbias) {
    dim3 g(N / 128, (M + 127) / 128);
    if (hasbias) {
        if (act) sgemm_kernel<1, true><<<g, 256>>>(A, B, bias, C, M, N, K);
        else     sgemm_kernel<0, true><<<g, 256>>>(A, B, bias, C, M, N, K);
    } else {
        if (act) sgemm_kernel<1, false><<<g, 256>>>(A, B, bias, C, M, N, K);
        else     sgemm_kernel<0, false><<<g, 256>>>(A, B, bias, C, M, N, K);
    }
}

template <typename T>
static T* symptr(const void* sym) {
    void* p = nullptr;
    cudaGetSymbolAddress(&p, sym);
    return (T*)p;
}

extern "C" void kernel_launch(void* const* d_in, const int* in_sizes, int n_in,
                              void* d_out, int out_size) {
    const float* x    = (const float*)d_in[0];
    const int*   ei   = (const int*)d_in[1];
    const int*   tgt  = (const int*)d_in[2];
    const float* ipW  = (const float*)d_in[3];
    const float* ipb  = (const float*)d_in[4];
    const float* gWx  = (const float*)d_in[5];
    const float* gWh  = (const float*)d_in[6];
    const float* gbx  = (const float*)d_in[7];
    const float* gbh  = (const float*)d_in[8];
    const float* dynW = (const float*)d_in[9];
    const float* dynb = (const float*)d_in[10];
    const float* g1W  = (const float*)d_in[11];
    const float* g1as = (const float*)d_in[12];
    const float* g1ad = (const float*)d_in[13];
    const float* g1b  = (const float*)d_in[14];
    const float* g2W  = (const float*)d_in[15];
    const float* g2as = (const float*)d_in[16];
    const float* g2ad = (const float*)d_in[17];
    const float* g2b  = (const float*)d_in[18];
    const float* fcW  = (const float*)d_in[19];
    const float* fcb  = (const float*)d_in[20];
    const float* l0Wx = (const float*)d_in[21];
    const float* l0Wh = (const float*)d_in[22];
    const float* l0b  = (const float*)d_in[23];
    const float* l1Wx = (const float*)d_in[24];
    const float* l1Wh = (const float*)d_in[25];
    const float* l1b  = (const float*)d_in[26];
    const float* opW  = (const float*)d_in[27];
    const float* opb  = (const float*)d_in[28];
    float* out = (float*)d_out;

    float* p_lh   = symptr<float>(d_lh);
    float* p_hist = symptr<float>(d_hist);
    float* p_feat = symptr<float>(d_feat);
    float* p_gat1 = symptr<float>(d_gat1);
    float* p_gat2 = symptr<float>(d_gat2);
    float* p_encT = symptr<float>(d_encT);
    float* p_enc  = symptr<float>(d_enc);
    float* p_xb0  = symptr<float>(d_xb0);
    float* p_h1a  = symptr<float>(d_h1all);
    int*   p_deg  = symptr<int>(d_deg);
    int*   p_cur  = symptr<int>(d_cur);

    const int GRU_SMEM = 128 * 384 * 4 + 128 * GP * 8 + 32 * GP * 8;     // ~207 KB
    const int DEC_SMEM = (1024 + 256 + 256) * DP * 8;                    // 144 KB
    cudaFuncSetAttribute(gru_kernel, cudaFuncAttributeMaxDynamicSharedMemorySize, GRU_SMEM);
    cudaFuncSetAttribute(decoder_kernel, cudaFuncAttributeMaxDynamicSharedMemorySize, DEC_SMEM);

    // ---- CSR build ----
    izero<<<(NN + 255) / 256, 256>>>(p_deg, NN);
    izero<<<(NN + 255) / 256, 256>>>(p_cur, NN);
    k_deg<<<(ET + 255) / 256, 256>>>(ei);
    k_scan<<<1, 1024>>>();
    k_fill<<<(ET + 255) / 256, 256>>>(ei);
    k_sort<<<(NN + 255) / 256, 256>>>();

    // ---- persistent GRU encoder (writes leaky(h) directly) ----
    gru_kernel<<<NN / GR, 256, GRU_SMEM>>>(x, ipW, ipb, gWx, gbx, gbh, gWh, p_lh);
    sgemm(p_lh, dynW, dynb, p_hist, NN, 128, 128, 1, true);

    // ---- GAT layer 1 ----
    sgemm(p_hist, g1W, nullptr, p_feat, NN, 384, 128, 0, false);
    gat_scores<<<NN, 96>>>(p_feat, g1as, g1ad);
    edge_scores<<<(ET + 255) / 256, 256>>>(ei);
    gat_aggregate<<<(NN * 3 + 3) / 4, 128>>>(ei, p_feat, g1b, p_gat1);

    // ---- GAT layer 2 ----
    sgemm(p_gat1, g2W, nullptr, p_feat, NN, 384, 384, 0, false);
    gat_scores<<<NN, 96>>>(p_feat, g2as, g2ad);
    edge_scores<<<(ET + 255) / 256, 256>>>(ei);
    gat_aggregate<<<(NN * 3 + 3) / 4, 128>>>(ei, p_feat, g2b, p_gat2);

    // ---- target gather + fc + layer0 input precompute ----
    k_gather<<<(NT * 384 + 255) / 256, 256>>>(tgt, p_gat2, p_encT);
    sgemm(p_encT, fcW, fcb, p_enc, NT, 128, 384, 1, true);
    sgemm(p_enc, l0Wx, l0b, p_xb0, NT, 1024, 128, 0, true);

    // ---- persistent decoder: all 25 steps, both LSTM layers, one launch ----
    decoder_kernel<<<NT / DR, 256, DEC_SMEM>>>(p_xb0, l0Wh, l1Wx, l1Wh, l1b, p_h1a);

    // ---- output head ----
    out_head<<<(NT * OUTL * 32 + 127) / 128, 128>>>(opW, opb, out);
}

// round 7
// speedup vs baseline: 1.9287x; 1.4282x over previous
#include <cuda_runtime.h>
#include <cuda_bf16.h>
#include <math.h>

#define NN 30000
#define NE 300000
#define NT 3000
#define ET (NE + NN)
#define OUTL 25

typedef unsigned long long ull;
typedef unsigned int u32;

// ---------------- scratch ------------------------------------------------------
__device__ float d_lh[NN * 128];
__device__ float d_hist[NN * 128];
__device__ float d_feat[NN * 384];
__device__ float d_gat1[NN * 384];
__device__ float d_gat2[NN * 384];
__device__ float d_ssrc[NN * 3];
__device__ float d_sdst[NN * 3];
__device__ float d_ev[ET * 3];
__device__ int   d_deg[NN];
__device__ int   d_off[NN + 1];
__device__ int   d_cur[NN];
__device__ int   d_eid[ET];
__device__ float d_encT[NT * 384];
__device__ float d_enc[NT * 128];
__device__ float d_xb0[NT * 1024];
__device__ float d_g0[NT * 1024];
__device__ float d_g1[NT * 1024];
__device__ float d_concat[NT * 512];
__device__ float d_c0[NT * 256];
__device__ float d_c1[NT * 256];
__device__ float d_wcat[512 * 1024];
__device__ float d_h1all[NT * OUTL * 256];

__device__ __forceinline__ float sigm(float x) { return 1.f / (1.f + __expf(-x)); }
__device__ __forceinline__ float lk1(float x) { return x >= 0.f ? x : 0.1f * x; }

// ---- packed fp32x2 helpers (GRU kernel) ---------------------------------------
__device__ __forceinline__ ull pdup(float w) {
    unsigned u = __float_as_uint(w);
    ull r;
    asm("mov.b64 %0, {%1, %1};" : "=l"(r) : "r"(u));
    return r;
}
__device__ __forceinline__ ull pk2(float a, float b) {
    unsigned ua = __float_as_uint(a), ub = __float_as_uint(b);
    ull r;
    asm("mov.b64 %0, {%1, %2};" : "=l"(r) : "r"(ua), "r"(ub));
    return r;
}
__device__ __forceinline__ float2 unpk(ull v) {
    unsigned a, b;
    asm("mov.b64 {%0, %1}, %2;" : "=r"(a), "=r"(b) : "l"(v));
    return make_float2(__uint_as_float(a), __uint_as_float(b));
}
__device__ __forceinline__ void fma2(ull& acc, ull a, ull b) {
    asm("fma.rn.f32x2 %0, %1, %2, %0;" : "+l"(acc) : "l"(a), "l"(b));
}

__device__ __forceinline__ u32 f2tf(float v) {
    u32 r;
    asm("cvt.rna.tf32.f32 %0, %1;" : "=r"(r) : "f"(v));
    return r;
}
__device__ __forceinline__ void mma_tf32(float* d, const u32* a, const u32* b) {
    asm("mma.sync.aligned.m16n8k8.row.col.f32.tf32.tf32.f32 "
        "{%0,%1,%2,%3}, {%4,%5,%6,%7}, {%8,%9}, {%0,%1,%2,%3};"
        : "+f"(d[0]), "+f"(d[1]), "+f"(d[2]), "+f"(d[3])
        : "r"(a[0]), "r"(a[1]), "r"(a[2]), "r"(a[3]), "r"(b[0]), "r"(b[1]));
}

// ---------------- tf32 MMA GEMM (single-buffered, conservative) ----------------
// C[M,N] = A[M,K] @ B[K,N] (+bias)(+leaky). N%128==0, K%16==0, lda = A row stride.
// 128x128 tile, BK=16, 8 warps (4 M x 2 N), warp tile 32x64.
template <int ACT, bool BIAS>
__global__ __launch_bounds__(256) void mma_gemm(
    const float* __restrict__ A, const float* __restrict__ B,
    const float* __restrict__ bias, float* __restrict__ C,
    int M, int N, int K, int lda) {
    __shared__ u32 As[16][132];
    __shared__ u32 Bs[16][132];
    const int tid = threadIdx.x;
    const int bn = blockIdx.x * 128;
    const int gm = blockIdx.y * 128;
    const int warp = tid >> 5, lane = tid & 31;
    const int wm = warp & 3, wn = warp >> 2;
    const int group = lane >> 2, tig = lane & 3;

    float acc[2][8][4];
#pragma unroll
    for (int i = 0; i < 2; i++)
#pragma unroll
        for (int j = 0; j < 8; j++)
#pragma unroll
            for (int q = 0; q < 4; q++) acc[i][j][q] = 0.f;

    for (int kbase = 0; kbase < K; kbase += 16) {
        // stage one 128x16 A tile + 16x128 B tile (each thread: 2 float4 pairs)
#pragma unroll
        for (int it = 0; it < 2; it++) {
            int f = tid + it * 256;
            int arow = f >> 2, kq = (f & 3) * 4;
            float4 av = make_float4(0.f, 0.f, 0.f, 0.f);
            if (gm + arow < M)
                av = *(const float4*)(A + (size_t)(gm + arow) * lda + kbase + kq);
            As[kq + 0][arow] = f2tf(av.x);
            As[kq + 1][arow] = f2tf(av.y);
            As[kq + 2][arow] = f2tf(av.z);
            As[kq + 3][arow] = f2tf(av.w);
            int krow = f >> 5, nq = (f & 31) * 4;
            float4 bv = *(const float4*)(B + (size_t)(kbase + krow) * N + bn + nq);
            Bs[krow][nq + 0] = f2tf(bv.x);
            Bs[krow][nq + 1] = f2tf(bv.y);
            Bs[krow][nq + 2] = f2tf(bv.z);
            Bs[krow][nq + 3] = f2tf(bv.w);
        }
        __syncthreads();
#pragma unroll
        for (int kk = 0; kk < 16; kk += 8) {
            u32 afr[2][4];
#pragma unroll
            for (int mf = 0; mf < 2; mf++) {
                int rb = wm * 32 + mf * 16 + group;
                afr[mf][0] = As[kk + tig][rb];
                afr[mf][1] = As[kk + tig][rb + 8];
                afr[mf][2] = As[kk + tig + 4][rb];
                afr[mf][3] = As[kk + tig + 4][rb + 8];
            }
#pragma unroll
            for (int nf = 0; nf < 8; nf++) {
                int nb = wn * 64 + nf * 8 + group;
                u32 bfr[2];
                bfr[0] = Bs[kk + tig][nb];
                bfr[1] = Bs[kk + tig + 4][nb];
                mma_tf32(acc[0][nf], afr[0], bfr);
                mma_tf32(acc[1][nf], afr[1], bfr);
            }
        }
        __syncthreads();
    }

    // epilogue
#pragma unroll
    for (int mf = 0; mf < 2; mf++) {
#pragma unroll
        for (int nf = 0; nf < 8; nf++) {
            int c = bn + wn * 64 + nf * 8 + 2 * tig;
            float b0 = 0.f, b1 = 0.f;
            if (BIAS) { b0 = bias[c]; b1 = bias[c + 1]; }
            int r0 = gm + wm * 32 + mf * 16 + group;
            if (r0 < M) {
                float v0 = acc[mf][nf][0] + b0, v1 = acc[mf][nf][1] + b1;
                if (ACT == 1) { v0 = lk1(v0); v1 = lk1(v1); }
                *(float2*)(C + (size_t)r0 * N + c) = make_float2(v0, v1);
            }
            int r1 = r0 + 8;
            if (r1 < M) {
                float v0 = acc[mf][nf][2] + b0, v1 = acc[mf][nf][3] + b1;
                if (ACT == 1) { v0 = lk1(v0); v1 = lk1(v1); }
                *(float2*)(C + (size_t)r1 * N + c) = make_float2(v0, v1);
            }
        }
    }
}

__global__ void izero(int* p, int n) {
    int i = blockIdx.x * blockDim.x + threadIdx.x;
    if (i < n) p[i] = 0;
}
__global__ void fzero(float* p, int n) {
    int i = blockIdx.x * blockDim.x + threadIdx.x;
    if (i < n) p[i] = 0.f;
}
// build [Wx1; Wh1] stacked (512 x 1024)
__global__ void k_wcat(const float* __restrict__ Wx1, const float* __restrict__ Wh1) {
    int i = blockIdx.x * blockDim.x + threadIdx.x;
    if (i >= 512 * 1024) return;
    int k = i >> 10, n = i & 1023;
    d_wcat[i] = k < 256 ? Wx1[k * 1024 + n] : Wh1[(k - 256) * 1024 + n];
}

// ---------------- persistent GRU encoder (unchanged, working) ------------------
#define GR 24
#define GP 12
#define GHP 6
__global__ __launch_bounds__(256, 1) void gru_kernel(
    const float* __restrict__ x, const float* __restrict__ ipW,
    const float* __restrict__ ipb, const float* __restrict__ Wx,
    const float* __restrict__ bx, const float* __restrict__ bh,
    const float* __restrict__ Wh, float* __restrict__ lh) {
    extern __shared__ float smem[];
    float* Whs = smem;
    ull* hs = (ull*)(smem + 128 * 384);
    ull* es = hs + 128 * GP;
    const int tid = threadIdx.x;
    const int half = tid >> 7, j = tid & 127;
    const int row0 = blockIdx.x * GR;

    for (int i = tid * 4; i < 128 * 384; i += 1024)
        *(float4*)(Whs + i) = *(const float4*)(Wh + i);
    for (int i = tid; i < 128 * GP; i += 256) hs[i] = 0ULL;

    ull bh2[3], bx2[3];
#pragma unroll
    for (int g = 0; g < 3; g++) {
        bh2[g] = pdup(bh[g * 128 + j]);
        bx2[g] = pdup(bx[g * 128 + j]);
    }
    __syncthreads();

    for (int t = 0; t < 16; t++) {
        for (int v = tid; v < GR * 32; v += 256) {
            int r = v >> 5, c = v & 31;
            float x0 = x[(size_t)(row0 + r) * 32 + t * 2];
            float x1 = x[(size_t)(row0 + r) * 32 + t * 2 + 1];
            ((float*)es)[c * GR + r] = lk1(fmaf(x0, ipW[c], fmaf(x1, ipW[32 + c], ipb[c])));
        }
        __syncthreads();

        ull ah[3][GHP], ax[3][GHP];
#pragma unroll
        for (int g = 0; g < 3; g++)
#pragma unroll
            for (int p = 0; p < GHP; p++) { ah[g][p] = bh2[g]; ax[g][p] = bx2[g]; }

#pragma unroll 2
        for (int k = 0; k < 128; k++) {
            ull wr = pdup(Whs[k * 384 + j]);
            ull wz = pdup(Whs[k * 384 + 128 + j]);
            ull wn = pdup(Whs[k * 384 + 256 + j]);
#pragma unroll
            for (int p = 0; p < GHP; p++) {
                ull h2 = hs[k * GP + half * GHP + p];
                fma2(ah[0][p], h2, wr);
                fma2(ah[1][p], h2, wz);
                fma2(ah[2][p], h2, wn);
            }
        }
#pragma unroll 2
        for (int k = 0; k < 32; k++) {
            ull wr = pdup(Wx[k * 384 + j]);
            ull wz = pdup(Wx[k * 384 + 128 + j]);
            ull wn = pdup(Wx[k * 384 + 256 + j]);
#pragma unroll
            for (int p = 0; p < GHP; p++) {
                ull e2 = es[k * GP + half * GHP + p];
                fma2(ax[0][p], e2, wr);
                fma2(ax[1][p], e2, wz);
                fma2(ax[2][p], e2, wn);
            }
        }
        __syncthreads();
#pragma unroll
        for (int p = 0; p < GHP; p++) {
            float2 hr = unpk(ah[0][p]), hz = unpk(ah[1][p]), hn = unpk(ah[2][p]);
            float2 xr = unpk(ax[0][p]), xz = unpk(ax[1][p]), xn = unpk(ax[2][p]);
            float2 ho = unpk(hs[j * GP + half * GHP + p]);
            float r0 = sigm(xr.x + hr.x), r1 = sigm(xr.y + hr.y);
            float z0 = sigm(xz.x + hz.x), z1 = sigm(xz.y + hz.y);
            float n0 = tanhf(xn.x + r0 * hn.x), n1 = tanhf(xn.y + r1 * hn.y);
            float h0 = (1.f - z0) * n0 + z0 * ho.x;
            float h1 = (1.f - z1) * n1 + z1 * ho.y;
            hs[j * GP + half * GHP + p] = pk2(h0, h1);
        }
        __syncthreads();
    }
#pragma unroll
    for (int p = 0; p < GHP; p++) {
        float2 h = unpk(hs[j * GP + half * GHP + p]);
        int r = row0 + 2 * (half * GHP + p);
        lh[(size_t)r * 128 + j] = lk1(h.x);
        lh[(size_t)(r + 1) * 128 + j] = lk1(h.y);
    }
}

// ---------------- LSTM combine kernels -----------------------------------------
__global__ void combine0(const float* __restrict__ xb0, const float* __restrict__ g0,
                         float* __restrict__ concat, float* __restrict__ c0) {
    int idx = blockIdx.x * blockDim.x + threadIdx.x;
    if (idx >= NT * 256) return;
    int i = idx >> 8, j = idx & 255;
    size_t base = (size_t)i * 1024;
    float gi = xb0[base + j] + g0[base + j];
    float gf = xb0[base + 256 + j] + g0[base + 256 + j];
    float gg = xb0[base + 512 + j] + g0[base + 512 + j];
    float go = xb0[base + 768 + j] + g0[base + 768 + j];
    float cv = sigm(gf) * c0[idx] + sigm(gi) * tanhf(gg);
    c0[idx] = cv;
    concat[(size_t)i * 512 + j] = sigm(go) * tanhf(cv);
}
__global__ void combine1(const float* __restrict__ g1, float* __restrict__ concat,
                         float* __restrict__ c1, float* __restrict__ h1all, int t) {
    int idx = blockIdx.x * blockDim.x + threadIdx.x;
    if (idx >= NT * 256) return;
    int i = idx >> 8, j = idx & 255;
    size_t base = (size_t)i * 1024;
    float gi = g1[base + j];
    float gf = g1[base + 256 + j];
    float gg = g1[base + 512 + j];
    float go = g1[base + 768 + j];
    float cv = sigm(gf) * c1[idx] + sigm(gi) * tanhf(gg);
    c1[idx] = cv;
    float hv = sigm(go) * tanhf(cv);
    concat[(size_t)i * 512 + 256 + j] = hv;
    h1all[((size_t)i * OUTL + t) * 256 + j] = hv;
}

// ---------------- CSR build ----------------------------------------------------
__global__ void k_deg(const int* __restrict__ ei) {
    int e = blockIdx.x * blockDim.x + threadIdx.x;
    if (e >= ET) return;
    int d = e < NE ? ei[NE + e] : e - NE;
    atomicAdd(&d_deg[d], 1);
}
__global__ void k_scan() {
    __shared__ int sums[1024];
    const int CH = (NN + 1023) / 1024;
    int t = threadIdx.x;
    int begin = t * CH;
    int s = 0;
    for (int i = 0; i < CH; i++) {
        int idx = begin + i;
        if (idx < NN) s += d_deg[idx];
    }
    sums[t] = s;
    __syncthreads();
    for (int off = 1; off < 1024; off <<= 1) {
        int v = sums[t];
        int add = (t >= off) ? sums[t - off] : 0;
        __syncthreads();
        sums[t] = v + add;
        __syncthreads();
    }
    int run = (t == 0) ? 0 : sums[t - 1];
    for (int i = 0; i < CH; i++) {
        int idx = begin + i;
        if (idx < NN) {
            d_off[idx] = run;
            run += d_deg[idx];
        }
    }
    if (t == 1023) d_off[NN] = sums[1023];
}
__global__ void k_fill(const int* __restrict__ ei) {
    int e = blockIdx.x * blockDim.x + threadIdx.x;
    if (e >= ET) return;
    int d = e < NE ? ei[NE + e] : e - NE;
    int p = atomicAdd(&d_cur[d], 1);
    d_eid[d_off[d] + p] = e;
}
__global__ void k_sort() {
    int d = blockIdx.x * blockDim.x + threadIdx.x;
    if (d >= NN) return;
    int b = d_off[d], e = d_off[d + 1];
    for (int i = b + 1; i < e; i++) {
        int key = d_eid[i];
        int j = i - 1;
        while (j >= b && d_eid[j] > key) {
            d_eid[j + 1] = d_eid[j];
            j--;
        }
        d_eid[j + 1] = key;
    }
}

// ---------------- GAT ----------------------------------------------------------
__global__ void gat_scores(const float* __restrict__ feat, const float* __restrict__ as,
                           const float* __restrict__ ad) {
    int n = blockIdx.x;
    int wid = threadIdx.x >> 5, lane = threadIdx.x & 31;
    const float* f = feat + (size_t)n * 384 + wid * 128;
    const float* A = as + wid * 128;
    const float* D = ad + wid * 128;
    float s = 0.f, d = 0.f;
#pragma unroll
    for (int k = lane; k < 128; k += 32) {
        float v = f[k];
        s += v * A[k];
        d += v * D[k];
    }
#pragma unroll
    for (int o = 16; o; o >>= 1) {
        s += __shfl_xor_sync(0xffffffffu, s, o);
        d += __shfl_xor_sync(0xffffffffu, d, o);
    }
    if (!lane) {
        d_ssrc[n * 3 + wid] = s;
        d_sdst[n * 3 + wid] = d;
    }
}
__global__ void edge_scores(const int* __restrict__ ei) {
    int e = blockIdx.x * blockDim.x + threadIdx.x;
    if (e >= ET) return;
    int s = e < NE ? ei[e] : e - NE;
    int d = e < NE ? ei[NE + e] : e - NE;
#pragma unroll
    for (int h = 0; h < 3; h++) {
        float v = d_ssrc[s * 3 + h] + d_sdst[d * 3 + h];
        d_ev[e * 3 + h] = v >= 0.f ? v : 0.2f * v;
    }
}
__global__ void gat_aggregate(const int* __restrict__ ei, const float* __restrict__ feat,
                              const float* __restrict__ bias, float* __restrict__ out) {
    int gw = (blockIdx.x * blockDim.x + threadIdx.x) >> 5;
    int lane = threadIdx.x & 31;
    if (gw >= NN * 3) return;
    int dst = gw / 3, hd = gw % 3;
    int b = d_off[dst], en = d_off[dst + 1];
    float m = -1e30f;
    for (int i = b; i < en; i++) m = fmaxf(m, d_ev[d_eid[i] * 3 + hd]);
    float denom = 0.f, a0 = 0.f, a1 = 0.f, a2 = 0.f, a3 = 0.f;
    for (int i = b; i < en; i++) {
        int e = d_eid[i];
        float w = __expf(d_ev[e * 3 + hd] - m);
        denom += w;
        int s = e < NE ? ei[e] : e - NE;
        const float* fr = feat + (size_t)s * 384 + hd * 128;
        a0 = fmaf(w, fr[lane], a0);
        a1 = fmaf(w, fr[lane + 32], a1);
        a2 = fmaf(w, fr[lane + 64], a2);
        a3 = fmaf(w, fr[lane + 96], a3);
    }
    float inv = 1.f / denom;
    size_t ob = (size_t)dst * 384 + hd * 128;
    out[ob + lane] = a0 * inv + bias[hd * 128 + lane];
    out[ob + lane + 32] = a1 * inv + bias[hd * 128 + lane + 32];
    out[ob + lane + 64] = a2 * inv + bias[hd * 128 + lane + 64];
    out[ob + lane + 96] = a3 * inv + bias[hd * 128 + lane + 96];
}

__global__ void k_gather(const int* __restrict__ tgt, const float* __restrict__ src,
                         float* __restrict__ dst) {
    int i = blockIdx.x * blockDim.x + threadIdx.x;
    if (i >= NT * 384) return;
    int r = i / 384, c = i - r * 384;
    dst[i] = src[(size_t)tgt[r] * 384 + c];
}

// output head
__global__ void out_head(const float* __restrict__ opW, const float* __restrict__ opb,
                         float* __restrict__ out) {
    int gw = (blockIdx.x * blockDim.x + threadIdx.x) >> 5;
    int lane = threadIdx.x & 31;
    if (gw >= NT * OUTL) return;
    const float* hr = d_h1all + (size_t)gw * 256;
    float s0 = 0.f, s1 = 0.f;
#pragma unroll
    for (int k = lane; k < 256; k += 32) {
        float h = hr[k];
        s0 = fmaf(h, opW[k * 2], s0);
        s1 = fmaf(h, opW[k * 2 + 1], s1);
    }
#pragma unroll
    for (int o = 16; o; o >>= 1) {
        s0 += __shfl_xor_sync(0xffffffffu, s0, o);
        s1 += __shfl_xor_sync(0xffffffffu, s1, o);
    }
    if (!lane) {
        out[(size_t)gw * 2] = s0 + opb[0];
        out[(size_t)gw * 2 + 1] = s1 + opb[1];
    }
}

// ---------------- host orchestration -------------------------------------------
static void gemm(const float* A, const float* B, const float* bias, float* C,
                 int M, int N, int K, int lda, int act, bool hasbias) {
    dim3 g(N / 128, (M + 127) / 128);
    if (hasbias) {
        if (act) mma_gemm<1, true><<<g, 256>>>(A, B, bias, C, M, N, K, lda);
        else     mma_gemm<0, true><<<g, 256>>>(A, B, bias, C, M, N, K, lda);
    } else {
        if (act) mma_gemm<1, false><<<g, 256>>>(A, B, bias, C, M, N, K, lda);
        else     mma_gemm<0, false><<<g, 256>>>(A, B, bias, C, M, N, K, lda);
    }
}

template <typename T>
static T* symptr(const void* sym) {
    void* p = nullptr;
    cudaGetSymbolAddress(&p, sym);
    return (T*)p;
}

extern "C" void kernel_launch(void* const* d_in, const int* in_sizes, int n_in,
                              void* d_out, int out_size) {
    const float* x    = (const float*)d_in[0];
    const int*   ei   = (const int*)d_in[1];
    const int*   tgt  = (const int*)d_in[2];
    const float* ipW  = (const float*)d_in[3];
    const float* ipb  = (const float*)d_in[4];
    const float* gWx  = (const float*)d_in[5];
    const float* gWh  = (const float*)d_in[6];
    const float* gbx  = (const float*)d_in[7];
    const float* gbh  = (const float*)d_in[8];
    const float* dynW = (const float*)d_in[9];
    const float* dynb = (const float*)d_in[10];
    const float* g1W  = (const float*)d_in[11];
    const float* g1as = (const float*)d_in[12];
    const float* g1ad = (const float*)d_in[13];
    const float* g1b  = (const float*)d_in[14];
    const float* g2W  = (const float*)d_in[15];
    const float* g2as = (const float*)d_in[16];
    const float* g2ad = (const float*)d_in[17];
    const float* g2b  = (const float*)d_in[18];
    const float* fcW  = (const float*)d_in[19];
    const float* fcb  = (const float*)d_in[20];
    const float* l0Wx = (const float*)d_in[21];
    const float* l0Wh = (const float*)d_in[22];
    const float* l0b  = (const float*)d_in[23];
    const float* l1Wx = (const float*)d_in[24];
    const float* l1Wh = (const float*)d_in[25];
    const float* l1b  = (const float*)d_in[26];
    const float* opW  = (const float*)d_in[27];
    const float* opb  = (const float*)d_in[28];
    float* out = (float*)d_out;

    float* p_lh    = symptr<float>(d_lh);
    float* p_hist  = symptr<float>(d_hist);
    float* p_feat  = symptr<float>(d_feat);
    float* p_gat1  = symptr<float>(d_gat1);
    float* p_gat2  = symptr<float>(d_gat2);
    float* p_encT  = symptr<float>(d_encT);
    float* p_enc   = symptr<float>(d_enc);
    float* p_xb0   = symptr<float>(d_xb0);
    float* p_g0    = symptr<float>(d_g0);
    float* p_g1    = symptr<float>(d_g1);
    float* p_cat   = symptr<float>(d_concat);
    float* p_c0    = symptr<float>(d_c0);
    float* p_c1    = symptr<float>(d_c1);
    float* p_wcat  = symptr<float>(d_wcat);
    float* p_h1a   = symptr<float>(d_h1all);
    int*   p_deg   = symptr<int>(d_deg);
    int*   p_cur   = symptr<int>(d_cur);

    const int GRU_SMEM = 128 * 384 * 4 + 128 * GP * 8 + 32 * GP * 8;
    cudaFuncSetAttribute(gru_kernel, cudaFuncAttributeMaxDynamicSharedMemorySize, GRU_SMEM);

    // ---- CSR build ----
    izero<<<(NN + 255) / 256, 256>>>(p_deg, NN);
    izero<<<(NN + 255) / 256, 256>>>(p_cur, NN);
    k_deg<<<(ET + 255) / 256, 256>>>(ei);
    k_scan<<<1, 1024>>>();
    k_fill<<<(ET + 255) / 256, 256>>>(ei);
    k_sort<<<(NN + 255) / 256, 256>>>();

    // ---- persistent GRU encoder ----
    gru_kernel<<<NN / GR, 256, GRU_SMEM>>>(x, ipW, ipb, gWx, gbx, gbh, gWh, p_lh);
    gemm(p_lh, dynW, dynb, p_hist, NN, 128, 128, 128, 1, true);

    // ---- GAT layer 1 ----
    gemm(p_hist, g1W, nullptr, p_feat, NN, 384, 128, 128, 0, false);
    gat_scores<<<NN, 96>>>(p_feat, g1as, g1ad);
    edge_scores<<<(ET + 255) / 256, 256>>>(ei);
    gat_aggregate<<<(NN * 3 + 3) / 4, 128>>>(ei, p_feat, g1b, p_gat1);

    // ---- GAT layer 2 ----
    gemm(p_gat1, g2W, nullptr, p_feat, NN, 384, 384, 384, 0, false);
    gat_scores<<<NN, 96>>>(p_feat, g2as, g2ad);
    edge_scores<<<(ET + 255) / 256, 256>>>(ei);
    gat_aggregate<<<(NN * 3 + 3) / 4, 128>>>(ei, p_feat, g2b, p_gat2);

    // ---- target gather + fc + layer0 input precompute ----
    k_gather<<<(NT * 384 + 255) / 256, 256>>>(tgt, p_gat2, p_encT);
    gemm(p_encT, fcW, fcb, p_enc, NT, 128, 384, 384, 1, true);
    gemm(p_enc, l0Wx, l0b, p_xb0, NT, 1024, 128, 128, 0, true);

    // ---- decoder: 25 steps, 2 tf32 GEMMs + 2 combines per step ----
    k_wcat<<<(512 * 1024 + 255) / 256, 256>>>(l1Wx, l1Wh);
    fzero<<<(NT * 512 + 255) / 256, 256>>>(p_cat, NT * 512);
    fzero<<<(NT * 256 + 255) / 256, 256>>>(p_c0, NT * 256);
    fzero<<<(NT * 256 + 255) / 256, 256>>>(p_c1, NT * 256);
    for (int t = 0; t < OUTL; t++) {
        // layer0: g0 = h0_prev @ Wh0  (h0_prev = concat[:,0:256], lda=512)
        gemm(p_cat, l0Wh, nullptr, p_g0, NT, 1024, 256, 512, 0, false);
        combine0<<<(NT * 256 + 255) / 256, 256>>>(p_xb0, p_g0, p_cat, p_c0);
        // layer1: g1 = [h0_new, h1_prev] @ [Wx1; Wh1] + b1  (K=512)
        gemm(p_cat, p_wcat, l1b, p_g1, NT, 1024, 512, 512, 0, true);
        combine1<<<(NT * 256 + 255) / 256, 256>>>(p_g1, p_cat, p_c1, p_h1a, t);
    }

    // ---- output head ----
    out_head<<<(NT * OUTL * 32 + 127) / 128, 128>>>(opW, opb, out);
}